// round 2
// baseline (speedup 1.0000x reference)
#include <cuda_runtime.h>
#include <math.h>

#define NN 50000
#define EE 400000
#define ET 450000      // EE + NN self loops
#define LN_EPS 1e-5f

// ---------------- scratch (device globals; allocation is forbidden) ----------
__device__ float g_h[(size_t)NN * 512];     // GEMM output per layer
__device__ float g_agg[(size_t)NN * 512];   // aggregation accumulator
__device__ float g_feat[(size_t)NN * 512];  // layer output / next input
__device__ float g_ssrc[NN * 4];
__device__ float g_sdst[NN * 4];
__device__ float g_m[NN * 4];
__device__ float g_den[NN * 4];
__device__ float g_ex[(size_t)ET * 4];      // per-edge exp(e - m[dst])

// ---------------- fp32 tiled GEMM: C[M,Ncol] = A[M,K] @ B[K,Ncol] ------------
// 64x64 tile, BK=16, 256 threads, 4x4 per thread. Ncol,K multiples of {64,16}.
__global__ void gemm64(const float* __restrict__ A, const float* __restrict__ B,
                       float* __restrict__ C, int M, int Ncol, int K) {
    __shared__ float As[16][64];
    __shared__ float Bs[16][64];
    int tid = threadIdx.x;
    int tx = tid & 15, ty = tid >> 4;
    int row0 = blockIdx.y * 64, col0 = blockIdx.x * 64;
    float acc[4][4] = {};
    int a_m = tid >> 2, a_k = (tid & 3) << 2;   // one float4 of A per thread
    int b_k = tid >> 4, b_n = (tid & 15) << 2;  // one float4 of B per thread
    for (int k0 = 0; k0 < K; k0 += 16) {
        float4 av;
        int ar = row0 + a_m;
        if (ar < M) av = *(const float4*)(A + (size_t)ar * K + k0 + a_k);
        else        av = make_float4(0.f, 0.f, 0.f, 0.f);
        As[a_k + 0][a_m] = av.x;
        As[a_k + 1][a_m] = av.y;
        As[a_k + 2][a_m] = av.z;
        As[a_k + 3][a_m] = av.w;
        *(float4*)(&Bs[b_k][b_n]) =
            *(const float4*)(B + (size_t)(k0 + b_k) * Ncol + col0 + b_n);
        __syncthreads();
#pragma unroll
        for (int k = 0; k < 16; k++) {
            float a[4], b[4];
#pragma unroll
            for (int i = 0; i < 4; i++) a[i] = As[k][ty * 4 + i];
#pragma unroll
            for (int j = 0; j < 4; j++) b[j] = Bs[k][tx * 4 + j];
#pragma unroll
            for (int i = 0; i < 4; i++)
#pragma unroll
                for (int j = 0; j < 4; j++) acc[i][j] += a[i] * b[j];
        }
        __syncthreads();
    }
#pragma unroll
    for (int i = 0; i < 4; i++) {
        int r = row0 + ty * 4 + i;
        if (r < M) {
#pragma unroll
            for (int j = 0; j < 4; j++)
                C[(size_t)r * Ncol + col0 + tx * 4 + j] = acc[i][j];
        }
    }
}

// ---------------- per-node attention scores: s = <h[n,h,:], a[h,:]> ----------
__global__ void scores_k(const float* __restrict__ h, const float* __restrict__ asrc,
                         const float* __restrict__ adst, float* __restrict__ ssrc,
                         float* __restrict__ sdst, int H, int C) {
    int warp = (blockIdx.x * blockDim.x + threadIdx.x) >> 5;
    int lane = threadIdx.x & 31;
    if (warp >= NN) return;
    int HC = H * C;
    for (int hd = 0; hd < H; hd++) {
        float ps = 0.f, pd = 0.f;
        for (int c = lane * 4; c < C; c += 128) {
            float4 hv = *(const float4*)(h + (size_t)warp * HC + hd * C + c);
            float4 as = *(const float4*)(asrc + hd * C + c);
            float4 ad = *(const float4*)(adst + hd * C + c);
            ps += hv.x * as.x + hv.y * as.y + hv.z * as.z + hv.w * as.w;
            pd += hv.x * ad.x + hv.y * ad.y + hv.z * ad.z + hv.w * ad.w;
        }
#pragma unroll
        for (int o = 16; o; o >>= 1) {
            ps += __shfl_down_sync(0xffffffffu, ps, o);
            pd += __shfl_down_sync(0xffffffffu, pd, o);
        }
        if (lane == 0) { ssrc[warp * H + hd] = ps; sdst[warp * H + hd] = pd; }
    }
}

// ---------------- init m/-inf, den/0, agg/0 ----------------------------------
__global__ void init_k(float* __restrict__ m, float* __restrict__ den,
                       float* __restrict__ agg, int NH, int NHC) {
    int stride = gridDim.x * blockDim.x;
    for (int i = blockIdx.x * blockDim.x + threadIdx.x; i < NHC; i += stride) {
        agg[i] = 0.f;
        if (i < NH) { m[i] = -INFINITY; den[i] = 0.f; }
    }
}

// order-preserving float atomic max (init must be -inf)
__device__ __forceinline__ void atomicMaxF(float* addr, float v) {
    if (v >= 0.f) atomicMax((int*)addr, __float_as_int(v));
    else          atomicMin((unsigned int*)addr, __float_as_uint(v));
}

// edge_index arrives as int32 (harness downcasts int64), row-major [2, E]
__device__ __forceinline__ void edge_nodes(int e, const int* ei, int& s, int& d) {
    if (e < EE) { s = ei[e]; d = ei[EE + e]; }
    else        { s = e - EE; d = s; }
}

// ---------------- pass 1: segment max of leaky_relu(s_src+s_dst) over dst ----
__global__ void edge_max_k(const int* __restrict__ ei, const float* __restrict__ ssrc,
                           const float* __restrict__ sdst, float* __restrict__ m, int H) {
    int e = blockIdx.x * blockDim.x + threadIdx.x;
    if (e >= ET) return;
    int s, d; edge_nodes(e, ei, s, d);
    for (int hd = 0; hd < H; hd++) {
        float v = ssrc[s * H + hd] + sdst[d * H + hd];
        v = v > 0.f ? v : 0.2f * v;
        atomicMaxF(&m[d * H + hd], v);
    }
}

// ---------------- pass 2: ex = exp(e - m[dst]); den[dst] += ex ---------------
__global__ void edge_exp_k(const int* __restrict__ ei, const float* __restrict__ ssrc,
                           const float* __restrict__ sdst, const float* __restrict__ m,
                           float* __restrict__ den, float* __restrict__ ex, int H) {
    int e = blockIdx.x * blockDim.x + threadIdx.x;
    if (e >= ET) return;
    int s, d; edge_nodes(e, ei, s, d);
    for (int hd = 0; hd < H; hd++) {
        float v = ssrc[s * H + hd] + sdst[d * H + hd];
        v = v > 0.f ? v : 0.2f * v;
        float x = expf(v - m[d * H + hd]);
        ex[(size_t)e * H + hd] = x;
        atomicAdd(&den[d * H + hd], x);
    }
}

// ---------------- pass 3: agg[dst] += ex * h[src] (warp per edge, float4) ----
__global__ void edge_agg_k(const int* __restrict__ ei, const float* __restrict__ h,
                           const float* __restrict__ ex, float* __restrict__ agg,
                           int H, int HC, int shiftC) {
    int gw = (blockIdx.x * blockDim.x + threadIdx.x) >> 5;
    int lane = threadIdx.x & 31;
    if (gw >= ET) return;
    int s, d; edge_nodes(gw, ei, s, d);
    const float* hp = h + (size_t)s * HC;
    float* ap = agg + (size_t)d * HC;
    for (int c = lane * 4; c < HC; c += 128) {
        float coef = ex[(size_t)gw * H + (c >> shiftC)];
        float4 hv = *(const float4*)(hp + c);
        atomicAdd(ap + c + 0, coef * hv.x);
        atomicAdd(ap + c + 1, coef * hv.y);
        atomicAdd(ap + c + 2, coef * hv.z);
        atomicAdd(ap + c + 3, coef * hv.w);
    }
}

// ---------------- GAT epilogue: /den + bias -> LN -> ELU ---------------------
__global__ void gat_fin_k(const float* __restrict__ agg, const float* __restrict__ den,
                          const float* __restrict__ bias, const float* __restrict__ lng,
                          const float* __restrict__ lnb, float* __restrict__ out,
                          int H, int HC, int shiftC) {
    __shared__ float sh[256];
    int n = blockIdx.x;
    int t = threadIdx.x;  // 128 threads
    float v[4];
    float sum = 0.f, sq = 0.f;
    int cnt = 0;
    for (int c = t; c < HC; c += 128) {
        float val = agg[(size_t)n * HC + c] / den[n * H + (c >> shiftC)] + bias[c];
        v[cnt++] = val; sum += val; sq += val * val;
    }
    sh[t] = sum; sh[128 + t] = sq;
    __syncthreads();
    for (int o = 64; o; o >>= 1) {
        if (t < o) { sh[t] += sh[t + o]; sh[128 + t] += sh[128 + t + o]; }
        __syncthreads();
    }
    float mu = sh[0] / HC;
    float var = sh[128] / HC - mu * mu;
    float rstd = rsqrtf(var + LN_EPS);
    cnt = 0;
    for (int c = t; c < HC; c += 128) {
        float y = (v[cnt++] - mu) * rstd * lng[c] + lnb[c];
        out[(size_t)n * HC + c] = y > 0.f ? y : expm1f(y);
    }
}

// ---------------- decoder epilogue: +bias -> LN -> ELU -----------------------
__global__ void ln_elu_k(const float* __restrict__ in, const float* __restrict__ bias,
                         const float* __restrict__ lng, const float* __restrict__ lnb,
                         float* __restrict__ out, int W) {
    __shared__ float sh[256];
    int n = blockIdx.x;
    int t = threadIdx.x;  // 128 threads
    float v[4];
    float sum = 0.f, sq = 0.f;
    int cnt = 0;
    for (int c = t; c < W; c += 128) {
        float val = in[(size_t)n * W + c] + bias[c];
        v[cnt++] = val; sum += val; sq += val * val;
    }
    sh[t] = sum; sh[128 + t] = sq;
    __syncthreads();
    for (int o = 64; o; o >>= 1) {
        if (t < o) { sh[t] += sh[t + o]; sh[128 + t] += sh[128 + t + o]; }
        __syncthreads();
    }
    float mu = sh[0] / W;
    float var = sh[128] / W - mu * mu;
    float rstd = rsqrtf(var + LN_EPS);
    cnt = 0;
    for (int c = t; c < W; c += 128) {
        float y = (v[cnt++] - mu) * rstd * lng[c] + lnb[c];
        out[(size_t)n * W + c] = y > 0.f ? y : expm1f(y);
    }
}

// ---------------- host orchestration -----------------------------------------
extern "C" void kernel_launch(void* const* d_in, const int* in_sizes, int n_in,
                              void* d_out, int out_size) {
    const float* x   = (const float*)d_in[0];
    const int*   ei  = (const int*)d_in[1];
    const float* W1  = (const float*)d_in[2];
    const float* a1s = (const float*)d_in[3];
    const float* a1d = (const float*)d_in[4];
    const float* b1  = (const float*)d_in[5];
    const float* g1  = (const float*)d_in[6];
    const float* bb1 = (const float*)d_in[7];
    const float* W2  = (const float*)d_in[8];
    const float* a2s = (const float*)d_in[9];
    const float* a2d = (const float*)d_in[10];
    const float* b2  = (const float*)d_in[11];
    const float* g2  = (const float*)d_in[12];
    const float* bb2 = (const float*)d_in[13];
    const float* W3  = (const float*)d_in[14];
    const float* a3s = (const float*)d_in[15];
    const float* a3d = (const float*)d_in[16];
    const float* b3  = (const float*)d_in[17];
    const float* g3  = (const float*)d_in[18];
    const float* bb3 = (const float*)d_in[19];
    const float* dW1   = (const float*)d_in[20];
    const float* db1   = (const float*)d_in[21];
    const float* lnd1g = (const float*)d_in[22];
    const float* lnd1b = (const float*)d_in[23];
    const float* dW2   = (const float*)d_in[24];
    const float* db2   = (const float*)d_in[25];
    const float* lnd2g = (const float*)d_in[26];
    const float* lnd2b = (const float*)d_in[27];

    float *h, *agg, *feat, *ssrc, *sdst, *m, *den, *ex;
    cudaGetSymbolAddress((void**)&h,    g_h);
    cudaGetSymbolAddress((void**)&agg,  g_agg);
    cudaGetSymbolAddress((void**)&feat, g_feat);
    cudaGetSymbolAddress((void**)&ssrc, g_ssrc);
    cudaGetSymbolAddress((void**)&sdst, g_sdst);
    cudaGetSymbolAddress((void**)&m,    g_m);
    cudaGetSymbolAddress((void**)&den,  g_den);
    cudaGetSymbolAddress((void**)&ex,   g_ex);

    const int MROWS = (NN + 63) / 64;

    // ---- one GAT layer ----
    auto gat = [&](const float* xin, int Fin, const float* W, const float* as_,
                   const float* ad_, const float* bias, const float* lg,
                   const float* lb, int H, int C, float* outf) {
        int HC = H * C;
        int shiftC = (C == 128) ? 7 : 6;
        gemm64<<<dim3(HC / 64, MROWS), 256>>>(xin, W, h, NN, HC, Fin);
        scores_k<<<(NN * 32 + 255) / 256, 256>>>(h, as_, ad_, ssrc, sdst, H, C);
        init_k<<<2048, 256>>>(m, den, agg, NN * H, NN * HC);
        edge_max_k<<<(ET + 255) / 256, 256>>>(ei, ssrc, sdst, m, H);
        edge_exp_k<<<(ET + 255) / 256, 256>>>(ei, ssrc, sdst, m, den, ex, H);
        edge_agg_k<<<(ET * 32 + 255) / 256, 256>>>(ei, h, ex, agg, H, HC, shiftC);
        gat_fin_k<<<NN, 128>>>(agg, den, bias, lg, lb, outf, H, HC, shiftC);
    };

    gat(x,    128, W1, a1s, a1d, b1, g1, bb1, 4, 128, feat);
    gat(feat, 512, W2, a2s, a2d, b2, g2, bb2, 2, 128, feat);
    gat(feat, 256, W3, a3s, a3d, b3, g3, bb3, 1,  64, feat);

    // ---- decoder ----
    gemm64<<<dim3(2, MROWS), 256>>>(feat, dW1, h, NN, 128, 64);
    ln_elu_k<<<NN, 128>>>(h, db1, lnd1g, lnd1b, feat, 128);
    gemm64<<<dim3(2, MROWS), 256>>>(feat, dW2, h, NN, 128, 128);
    ln_elu_k<<<NN, 128>>>(h, db2, lnd2g, lnd2b, (float*)d_out, 128);
}

// round 3
// speedup vs baseline: 1.4798x; 1.4798x over previous
#include <cuda_runtime.h>
#include <math.h>
#include <stdint.h>

#define NN 50000
#define EE 400000
#define ET 450000      // EE + NN self loops
#define LN_EPS 1e-5f

// ---------------- scratch (device globals; allocation is forbidden) ----------
__device__ float g_h[(size_t)NN * 512];     // GEMM output per layer
__device__ float g_agg[(size_t)NN * 512];   // aggregation accumulator
__device__ float g_feat[(size_t)NN * 512];  // layer output / next input
__device__ float g_ssrc[NN * 4];
__device__ float g_sdst[NN * 4];
__device__ float g_m[NN * 4];
__device__ float g_den[NN * 4];
__device__ float g_ex[(size_t)ET * 4];      // per-edge exp(e - m[dst])

// ---------------- 3xTF32 tensor-core GEMM ------------------------------------
// C[M,N] = A[M,K] @ B[K,N], all row-major fp32.
// Block tile 128x64, BK=16, 256 threads (8 warps, 4x2), warp tile 32x32.
// Each operand split hi/lo in tf32; acc += Ah*Bh + Ah*Bl + Al*Bh (~fp32 accuracy).
// Requires: N % 64 == 0, K % 16 == 0. M arbitrary (row-guarded).

__device__ __forceinline__ uint32_t f2tf32(float x) {
    uint32_t r;
    asm("cvt.rna.tf32.f32 %0, %1;" : "=r"(r) : "f"(x));
    return r;
}

__device__ __forceinline__ void mma_tf32(float* c, const float* a, const float* b) {
    asm volatile(
        "mma.sync.aligned.m16n8k8.row.col.f32.tf32.tf32.f32 "
        "{%0,%1,%2,%3}, {%4,%5,%6,%7}, {%8,%9}, {%0,%1,%2,%3};"
        : "+f"(c[0]), "+f"(c[1]), "+f"(c[2]), "+f"(c[3])
        : "r"(__float_as_uint(a[0])), "r"(__float_as_uint(a[1])),
          "r"(__float_as_uint(a[2])), "r"(__float_as_uint(a[3])),
          "r"(__float_as_uint(b[0])), "r"(__float_as_uint(b[1])));
}

__global__ __launch_bounds__(256) void gemm_tf32(
        const float* __restrict__ A, const float* __restrict__ B,
        float* __restrict__ C, int M, int N, int K) {
    // strides 136/72: stride % 32 == 8 -> conflict-free fragment LDS
    __shared__ float Ah[16][136], Al[16][136];
    __shared__ float Bh[16][72],  Bl[16][72];

    int tid = threadIdx.x;
    int lane = tid & 31, wid = tid >> 5;
    int wm = (wid >> 1) * 32;       // warp row offset in tile (0,32,64,96)
    int wn = (wid & 1) * 32;        // warp col offset in tile (0,32)
    int q = lane & 3, t4 = lane >> 2;
    int row0 = blockIdx.y * 128, col0 = blockIdx.x * 64;

    float acc[2][4][4];
#pragma unroll
    for (int i = 0; i < 2; i++)
#pragma unroll
        for (int j = 0; j < 4; j++)
#pragma unroll
            for (int k = 0; k < 4; k++) acc[i][j][k] = 0.f;

    for (int k0 = 0; k0 < K; k0 += 16) {
        // load A tile 128x16 (2 float4 per thread), convert, store transposed
#pragma unroll
        for (int i = 0; i < 2; i++) {
            int j = tid + 256 * i;
            int r = j >> 2, c = (j & 3) << 2;
            float4 v;
            if (row0 + r < M) v = *(const float4*)(A + (size_t)(row0 + r) * K + k0 + c);
            else              v = make_float4(0.f, 0.f, 0.f, 0.f);
            float vv[4] = {v.x, v.y, v.z, v.w};
#pragma unroll
            for (int t = 0; t < 4; t++) {
                uint32_t hb = f2tf32(vv[t]);
                float hf = __uint_as_float(hb);
                Ah[c + t][r] = hf;
                Al[c + t][r] = __uint_as_float(f2tf32(vv[t] - hf));
            }
        }
        // load B tile 16x64 (1 float4 per thread)
        {
            int r = tid >> 4, c = (tid & 15) << 2;
            float4 v = *(const float4*)(B + (size_t)(k0 + r) * N + col0 + c);
            float vv[4] = {v.x, v.y, v.z, v.w};
            float4 h4, l4;
            float* hp = &h4.x; float* lp = &l4.x;
#pragma unroll
            for (int t = 0; t < 4; t++) {
                uint32_t hb = f2tf32(vv[t]);
                float hf = __uint_as_float(hb);
                hp[t] = hf;
                lp[t] = __uint_as_float(f2tf32(vv[t] - hf));
            }
            *(float4*)(&Bh[r][c]) = h4;
            *(float4*)(&Bl[r][c]) = l4;
        }
        __syncthreads();

#pragma unroll
        for (int kk = 0; kk < 16; kk += 8) {
            float ah[2][4], al[2][4], bh[4][2], bl[4][2];
#pragma unroll
            for (int mt = 0; mt < 2; mt++) {
                int m0 = wm + mt * 16 + t4;
                ah[mt][0] = Ah[kk + q][m0];     ah[mt][1] = Ah[kk + q][m0 + 8];
                ah[mt][2] = Ah[kk + q + 4][m0]; ah[mt][3] = Ah[kk + q + 4][m0 + 8];
                al[mt][0] = Al[kk + q][m0];     al[mt][1] = Al[kk + q][m0 + 8];
                al[mt][2] = Al[kk + q + 4][m0]; al[mt][3] = Al[kk + q + 4][m0 + 8];
            }
#pragma unroll
            for (int nt = 0; nt < 4; nt++) {
                int n0 = wn + nt * 8 + t4;
                bh[nt][0] = Bh[kk + q][n0]; bh[nt][1] = Bh[kk + q + 4][n0];
                bl[nt][0] = Bl[kk + q][n0]; bl[nt][1] = Bl[kk + q + 4][n0];
            }
#pragma unroll
            for (int mt = 0; mt < 2; mt++)
#pragma unroll
                for (int nt = 0; nt < 4; nt++) {
                    mma_tf32(acc[mt][nt], ah[mt], bh[nt]);
                    mma_tf32(acc[mt][nt], ah[mt], bl[nt]);
                    mma_tf32(acc[mt][nt], al[mt], bh[nt]);
                }
        }
        __syncthreads();
    }

    // store C
#pragma unroll
    for (int mt = 0; mt < 2; mt++) {
        int r0 = row0 + wm + mt * 16 + t4;
#pragma unroll
        for (int nt = 0; nt < 4; nt++) {
            int cc = col0 + wn + nt * 8 + q * 2;
            if (r0 < M) {
                C[(size_t)r0 * N + cc]     = acc[mt][nt][0];
                C[(size_t)r0 * N + cc + 1] = acc[mt][nt][1];
            }
            if (r0 + 8 < M) {
                C[(size_t)(r0 + 8) * N + cc]     = acc[mt][nt][2];
                C[(size_t)(r0 + 8) * N + cc + 1] = acc[mt][nt][3];
            }
        }
    }
}

// ---------------- per-node attention scores: s = <h[n,h,:], a[h,:]> ----------
__global__ void scores_k(const float* __restrict__ h, const float* __restrict__ asrc,
                         const float* __restrict__ adst, float* __restrict__ ssrc,
                         float* __restrict__ sdst, int H, int C) {
    int warp = (blockIdx.x * blockDim.x + threadIdx.x) >> 5;
    int lane = threadIdx.x & 31;
    if (warp >= NN) return;
    int HC = H * C;
    for (int hd = 0; hd < H; hd++) {
        float ps = 0.f, pd = 0.f;
        for (int c = lane * 4; c < C; c += 128) {
            float4 hv = *(const float4*)(h + (size_t)warp * HC + hd * C + c);
            float4 as = *(const float4*)(asrc + hd * C + c);
            float4 ad = *(const float4*)(adst + hd * C + c);
            ps += hv.x * as.x + hv.y * as.y + hv.z * as.z + hv.w * as.w;
            pd += hv.x * ad.x + hv.y * ad.y + hv.z * ad.z + hv.w * ad.w;
        }
#pragma unroll
        for (int o = 16; o; o >>= 1) {
            ps += __shfl_down_sync(0xffffffffu, ps, o);
            pd += __shfl_down_sync(0xffffffffu, pd, o);
        }
        if (lane == 0) { ssrc[warp * H + hd] = ps; sdst[warp * H + hd] = pd; }
    }
}

// ---------------- init m/-inf, den/0, agg/0 ----------------------------------
__global__ void init_k(float* __restrict__ m, float* __restrict__ den,
                       float* __restrict__ agg, int NH, int NHC) {
    int stride = gridDim.x * blockDim.x;
    for (int i = blockIdx.x * blockDim.x + threadIdx.x; i < NHC; i += stride) {
        agg[i] = 0.f;
        if (i < NH) { m[i] = -INFINITY; den[i] = 0.f; }
    }
}

// order-preserving float atomic max (init must be -inf)
__device__ __forceinline__ void atomicMaxF(float* addr, float v) {
    if (v >= 0.f) atomicMax((int*)addr, __float_as_int(v));
    else          atomicMin((unsigned int*)addr, __float_as_uint(v));
}

// edge_index arrives as int32 (harness downcasts int64), row-major [2, E]
__device__ __forceinline__ void edge_nodes(int e, const int* ei, int& s, int& d) {
    if (e < EE) { s = ei[e]; d = ei[EE + e]; }
    else        { s = e - EE; d = s; }
}

// ---------------- pass 1: segment max of leaky_relu(s_src+s_dst) over dst ----
__global__ void edge_max_k(const int* __restrict__ ei, const float* __restrict__ ssrc,
                           const float* __restrict__ sdst, float* __restrict__ m, int H) {
    int e = blockIdx.x * blockDim.x + threadIdx.x;
    if (e >= ET) return;
    int s, d; edge_nodes(e, ei, s, d);
    for (int hd = 0; hd < H; hd++) {
        float v = ssrc[s * H + hd] + sdst[d * H + hd];
        v = v > 0.f ? v : 0.2f * v;
        atomicMaxF(&m[d * H + hd], v);
    }
}

// ---------------- pass 2: ex = exp(e - m[dst]); den[dst] += ex ---------------
__global__ void edge_exp_k(const int* __restrict__ ei, const float* __restrict__ ssrc,
                           const float* __restrict__ sdst, const float* __restrict__ m,
                           float* __restrict__ den, float* __restrict__ ex, int H) {
    int e = blockIdx.x * blockDim.x + threadIdx.x;
    if (e >= ET) return;
    int s, d; edge_nodes(e, ei, s, d);
    for (int hd = 0; hd < H; hd++) {
        float v = ssrc[s * H + hd] + sdst[d * H + hd];
        v = v > 0.f ? v : 0.2f * v;
        float x = expf(v - m[d * H + hd]);
        ex[(size_t)e * H + hd] = x;
        atomicAdd(&den[d * H + hd], x);
    }
}

// ---------------- pass 3: agg[dst] += ex * h[src] (warp/edge, v4 RED) --------
__global__ void edge_agg_k(const int* __restrict__ ei, const float* __restrict__ h,
                           const float* __restrict__ ex, float* __restrict__ agg,
                           int H, int HC, int shiftC) {
    int gw = (blockIdx.x * blockDim.x + threadIdx.x) >> 5;
    int lane = threadIdx.x & 31;
    if (gw >= ET) return;
    int s, d; edge_nodes(gw, ei, s, d);
    const float* hp = h + (size_t)s * HC;
    float* ap = agg + (size_t)d * HC;
    for (int c = lane * 4; c < HC; c += 128) {
        float coef = ex[(size_t)gw * H + (c >> shiftC)];
        float4 hv = *(const float4*)(hp + c);
        asm volatile("red.global.add.v4.f32 [%0], {%1,%2,%3,%4};"
                     :: "l"(ap + c), "f"(coef * hv.x), "f"(coef * hv.y),
                        "f"(coef * hv.z), "f"(coef * hv.w)
                     : "memory");
    }
}

// ---------------- GAT epilogue: /den + bias -> LN -> ELU ---------------------
__global__ void gat_fin_k(const float* __restrict__ agg, const float* __restrict__ den,
                          const float* __restrict__ bias, const float* __restrict__ lng,
                          const float* __restrict__ lnb, float* __restrict__ out,
                          int H, int HC, int shiftC) {
    __shared__ float sh[256];
    int n = blockIdx.x;
    int t = threadIdx.x;  // 128 threads
    float v[4];
    float sum = 0.f, sq = 0.f;
    int cnt = 0;
    for (int c = t; c < HC; c += 128) {
        float val = agg[(size_t)n * HC + c] / den[n * H + (c >> shiftC)] + bias[c];
        v[cnt++] = val; sum += val; sq += val * val;
    }
    sh[t] = sum; sh[128 + t] = sq;
    __syncthreads();
    for (int o = 64; o; o >>= 1) {
        if (t < o) { sh[t] += sh[t + o]; sh[128 + t] += sh[128 + t + o]; }
        __syncthreads();
    }
    float mu = sh[0] / HC;
    float var = sh[128] / HC - mu * mu;
    float rstd = rsqrtf(var + LN_EPS);
    cnt = 0;
    for (int c = t; c < HC; c += 128) {
        float y = (v[cnt++] - mu) * rstd * lng[c] + lnb[c];
        out[(size_t)n * HC + c] = y > 0.f ? y : expm1f(y);
    }
}

// ---------------- decoder epilogue: +bias -> LN -> ELU -----------------------
__global__ void ln_elu_k(const float* __restrict__ in, const float* __restrict__ bias,
                         const float* __restrict__ lng, const float* __restrict__ lnb,
                         float* __restrict__ out, int W) {
    __shared__ float sh[256];
    int n = blockIdx.x;
    int t = threadIdx.x;  // 128 threads
    float v[4];
    float sum = 0.f, sq = 0.f;
    int cnt = 0;
    for (int c = t; c < W; c += 128) {
        float val = in[(size_t)n * W + c] + bias[c];
        v[cnt++] = val; sum += val; sq += val * val;
    }
    sh[t] = sum; sh[128 + t] = sq;
    __syncthreads();
    for (int o = 64; o; o >>= 1) {
        if (t < o) { sh[t] += sh[t + o]; sh[128 + t] += sh[128 + t + o]; }
        __syncthreads();
    }
    float mu = sh[0] / W;
    float var = sh[128] / W - mu * mu;
    float rstd = rsqrtf(var + LN_EPS);
    cnt = 0;
    for (int c = t; c < W; c += 128) {
        float y = (v[cnt++] - mu) * rstd * lng[c] + lnb[c];
        out[(size_t)n * W + c] = y > 0.f ? y : expm1f(y);
    }
}

// ---------------- host orchestration -----------------------------------------
extern "C" void kernel_launch(void* const* d_in, const int* in_sizes, int n_in,
                              void* d_out, int out_size) {
    const float* x   = (const float*)d_in[0];
    const int*   ei  = (const int*)d_in[1];
    const float* W1  = (const float*)d_in[2];
    const float* a1s = (const float*)d_in[3];
    const float* a1d = (const float*)d_in[4];
    const float* b1  = (const float*)d_in[5];
    const float* g1  = (const float*)d_in[6];
    const float* bb1 = (const float*)d_in[7];
    const float* W2  = (const float*)d_in[8];
    const float* a2s = (const float*)d_in[9];
    const float* a2d = (const float*)d_in[10];
    const float* b2  = (const float*)d_in[11];
    const float* g2  = (const float*)d_in[12];
    const float* bb2 = (const float*)d_in[13];
    const float* W3  = (const float*)d_in[14];
    const float* a3s = (const float*)d_in[15];
    const float* a3d = (const float*)d_in[16];
    const float* b3  = (const float*)d_in[17];
    const float* g3  = (const float*)d_in[18];
    const float* bb3 = (const float*)d_in[19];
    const float* dW1   = (const float*)d_in[20];
    const float* db1   = (const float*)d_in[21];
    const float* lnd1g = (const float*)d_in[22];
    const float* lnd1b = (const float*)d_in[23];
    const float* dW2   = (const float*)d_in[24];
    const float* db2   = (const float*)d_in[25];
    const float* lnd2g = (const float*)d_in[26];
    const float* lnd2b = (const float*)d_in[27];

    float *h, *agg, *feat, *ssrc, *sdst, *m, *den, *ex;
    cudaGetSymbolAddress((void**)&h,    g_h);
    cudaGetSymbolAddress((void**)&agg,  g_agg);
    cudaGetSymbolAddress((void**)&feat, g_feat);
    cudaGetSymbolAddress((void**)&ssrc, g_ssrc);
    cudaGetSymbolAddress((void**)&sdst, g_sdst);
    cudaGetSymbolAddress((void**)&m,    g_m);
    cudaGetSymbolAddress((void**)&den,  g_den);
    cudaGetSymbolAddress((void**)&ex,   g_ex);

    const int MB = (NN + 127) / 128;  // gemm row blocks

    // ---- one GAT layer ----
    auto gat = [&](const float* xin, int Fin, const float* W, const float* as_,
                   const float* ad_, const float* bias, const float* lg,
                   const float* lb, int H, int C, float* outf) {
        int HC = H * C;
        int shiftC = (C == 128) ? 7 : 6;
        gemm_tf32<<<dim3(HC / 64, MB), 256>>>(xin, W, h, NN, HC, Fin);
        scores_k<<<(NN * 32 + 255) / 256, 256>>>(h, as_, ad_, ssrc, sdst, H, C);
        init_k<<<2048, 256>>>(m, den, agg, NN * H, NN * HC);
        edge_max_k<<<(ET + 255) / 256, 256>>>(ei, ssrc, sdst, m, H);
        edge_exp_k<<<(ET + 255) / 256, 256>>>(ei, ssrc, sdst, m, den, ex, H);
        edge_agg_k<<<(ET * 32 + 255) / 256, 256>>>(ei, h, ex, agg, H, HC, shiftC);
        gat_fin_k<<<NN, 128>>>(agg, den, bias, lg, lb, outf, H, HC, shiftC);
    };

    gat(x,    128, W1, a1s, a1d, b1, g1, bb1, 4, 128, feat);
    gat(feat, 512, W2, a2s, a2d, b2, g2, bb2, 2, 128, feat);
    gat(feat, 256, W3, a3s, a3d, b3, g3, bb3, 1,  64, feat);

    // ---- decoder ----
    gemm_tf32<<<dim3(2, MB), 256>>>(feat, dW1, h, NN, 128, 64);
    ln_elu_k<<<NN, 128>>>(h, db1, lnd1g, lnd1b, feat, 128);
    gemm_tf32<<<dim3(2, MB), 256>>>(feat, dW2, h, NN, 128, 128);
    ln_elu_k<<<NN, 128>>>(h, db2, lnd2g, lnd2b, (float*)d_out, 128);
}